// round 1
// baseline (speedup 1.0000x reference)
#include <cuda_runtime.h>
#include <math.h>

// MultiHeadsAttModel: hyperbolic (Poincare-ball) multi-head attention.
// Inputs (metadata order):
//   d_in[0] in_feats f32 [4,2000,32]        (256000)
//   d_in[1] in_nei   f32 [4,2000,5,2000]    (80,000,000)  -- dense one-hot adjacency
//   d_in[2] W1       f32 [160,32]
//   d_in[3] b1       f32 [160]
//   d_in[4] W2       f32 [32,32]
//   d_in[5] b2       f32 [32]
//   d_in[6] h_dim (int, unused), d_in[7] head (int, unused)
// Output: concat( out f32 [4,2000,32] = 256000 , att f32 [4,2000,5,5] = 200000 )

#define BB   4
#define NN   2000
#define KK   5
#define DD   32
#define M1   160
#define NT   160       // threads per block (5 warps)
#define MINN 1e-15f
#define MAXN 0.996f    // (1 - 4e-3)/sqrt(c), c = 1

__device__ __forceinline__ float artanhf_(float x) {
    const float lim = 1.0f - 1e-7f;
    x = fminf(fmaxf(x, -lim), lim);
    return 0.5f * (log1pf(x) - log1pf(-x));
}

__global__ void __launch_bounds__(NT)
mha_hyp_kernel(const float* __restrict__ in_feats,
               const float* __restrict__ in_nei,
               const float* __restrict__ W1,
               const float* __restrict__ b1,
               const float* __restrict__ W2,
               const float* __restrict__ b2,
               float* __restrict__ out,
               float* __restrict__ att_out) {
    __shared__ float W1T[DD][M1];     // W1 transposed: [d][row]
    __shared__ float W2T[DD][DD];     // W2 transposed
    __shared__ float sp[6][DD];       // agent + 5 neighbor points
    __shared__ float skv[6][M1];      // logmap0(hnn_layer(...)) for q(0) and kv(1..5)
    __shared__ float shb1[M1];
    __shared__ float shb2[DD];
    __shared__ float wpart[5][12];    // warp partials
    __shared__ float satt[25];
    __shared__ float s_pn[6], s_ps[6], s_cA[6], s_cB[6], s_l[6], s_q[6];
    __shared__ float s_hbf1, s_hbn21, s_hbf2, s_hbn22;
    __shared__ int   snei[KK];

    const int tid  = threadIdx.x;
    const int lane = tid & 31;
    const int warp = tid >> 5;
    const int bn   = blockIdx.x;     // 0..7999
    const int b    = bn / NN;
    const int n    = bn - b * NN;

    // ---- stage weights into shared (transposed for conflict-free matvec) ----
    for (int i = tid; i < M1 * DD; i += NT) {
        W1T[i & 31][i >> 5] = W1[i];
    }
    for (int i = tid; i < DD * DD; i += NT) {
        W2T[i & 31][i >> 5] = W2[i];
    }

    // ---- scan this agent's 5 one-hot rows (contiguous 10000 floats) ----
    {
        const float4* nin = (const float4*)(in_nei + (size_t)bn * (KK * NN));
        #pragma unroll 4
        for (int i = tid; i < (KK * NN) / 4; i += NT) {
            float4 v = nin[i];
            int c = i * 4;
            if (v.x != 0.f) { snei[c / NN] = c % NN; }
            if (v.y != 0.f) { int g = c + 1; snei[g / NN] = g % NN; }
            if (v.z != 0.f) { int g = c + 2; snei[g / NN] = g % NN; }
            if (v.w != 0.f) { int g = c + 3; snei[g / NN] = g % NN; }
        }
    }
    float bt  = b1[tid];
    float bt2 = (tid < DD) ? b2[tid] : 0.f;
    __syncthreads();

    // ---- gather 6 input rows: v=0 agent, v=1..5 neighbors ----
    for (int j = tid; j < 6 * DD; j += NT) {
        int v = j >> 5, d = j & 31;
        int row = (v == 0) ? n : snei[v - 1];
        sp[v][d] = in_feats[((size_t)b * NN + row) * DD + d];
    }
    __syncthreads();

    // ---- norms of 6 raw vectors + b1 + b2 ; point = proj(expmap0(logmap0(x))) ----
    {
        float vals[8];
        #pragma unroll
        for (int v = 0; v < 6; v++)
            vals[v] = (tid < DD) ? sp[v][tid] * sp[v][tid] : 0.f;
        vals[6] = bt * bt;
        vals[7] = bt2 * bt2;
        #pragma unroll
        for (int i = 0; i < 8; i++) {
            float x = vals[i];
            #pragma unroll
            for (int o = 16; o > 0; o >>= 1) x += __shfl_xor_sync(0xffffffffu, x, o);
            if (lane == 0) wpart[warp][i] = x;
        }
        __syncthreads();
        if (tid < 6) {
            float n2 = 0.f;
            for (int w = 0; w < 5; w++) n2 += wpart[w][tid];
            float xn = fmaxf(sqrtf(n2), MINN);
            float f1 = artanhf_(xn) / xn;          // logmap0 factor
            float fn = fmaxf(f1 * xn, MINN);
            float e  = tanhf(fn) / fn;             // expmap0 factor
            float pn = e * fn;
            float pj = (pn > MAXN) ? MAXN / pn : 1.f;
            s_ps[tid] = f1 * e * pj;
            s_pn[tid] = fmaxf(pj * pn, MINN);
        } else if (tid == 6 || tid == 7) {
            float n2 = 0.f;
            for (int w = 0; w < 5; w++) n2 += wpart[w][tid];
            float bnn = fmaxf(sqrtf(n2), MINN);
            float e  = tanhf(bnn) / bnn;           // hb = proj(expmap0(b))
            float pn = e * bnn;
            float pj = (pn > MAXN) ? MAXN / pn : 1.f;
            float f = e * pj;
            if (tid == 6) { s_hbf1 = f; s_hbn21 = f * f * n2; }
            else          { s_hbf2 = f; s_hbn22 = f * f * n2; }
        }
        __syncthreads();
    }
    for (int j = tid; j < 6 * DD; j += NT) {
        sp[j >> 5][j & 31] *= s_ps[j >> 5];
    }
    shb1[tid] = bt * s_hbf1;
    if (tid < DD) shb2[tid] = bt2 * s_hbf2;
    __syncthreads();

    // ---- layer 1: mx = W1 @ p, 6 vectors at once; thread t owns output row t ----
    float mx[6] = {0.f, 0.f, 0.f, 0.f, 0.f, 0.f};
    #pragma unroll 8
    for (int d = 0; d < DD; d++) {
        float w = W1T[d][tid];
        #pragma unroll
        for (int v = 0; v < 6; v++) mx[v] += w * sp[v][d];
    }
    // reduce: ||mx||^2 (6) and <mx, hb1> (6); then mobius_matvec+proj+mobius_add coefs
    {
        float hbv = shb1[tid];
        #pragma unroll
        for (int i = 0; i < 12; i++) {
            float x = (i < 6) ? mx[i] * mx[i] : mx[i - 6] * hbv;
            #pragma unroll
            for (int o = 16; o > 0; o >>= 1) x += __shfl_xor_sync(0xffffffffu, x, o);
            if (lane == 0) wpart[warp][i] = x;
        }
        __syncthreads();
        if (tid < 6) {
            float mxn2 = 0.f, mh = 0.f;
            for (int w = 0; w < 5; w++) { mxn2 += wpart[w][tid]; mh += wpart[w][6 + tid]; }
            float xn  = s_pn[tid];
            float mxn = fmaxf(sqrtf(mxn2), MINN);
            float rfac = (mxn2 == 0.f) ? 0.f
                       : tanhf(mxn / xn * artanhf_(xn)) / mxn;     // mobius_matvec
            float rn = rfac * mxn;
            float pj = (rn > MAXN) ? MAXN / fmaxf(rn, MINN) : 1.f; // proj
            float g  = pj * rfac;                                  // res' = g*mx
            float x2 = g * g * mxn2;
            float xy = g * mh;
            float y2 = s_hbn21;
            float A   = 1.f + 2.f * xy + y2;
            float Bc  = 1.f - x2;
            float den = fmaxf(1.f + 2.f * xy + x2 * y2, MINN);     // mobius_add
            s_cA[tid] = A * g / den;
            s_cB[tid] = Bc / den;
        }
        __syncthreads();
    }
    // c-vector, proj + logmap0 scale
    float cv[6];
    {
        float hbv = shb1[tid];
        #pragma unroll
        for (int v = 0; v < 6; v++) cv[v] = s_cA[v] * mx[v] + s_cB[v] * hbv;
        #pragma unroll
        for (int i = 0; i < 6; i++) {
            float x = cv[i] * cv[i];
            #pragma unroll
            for (int o = 16; o > 0; o >>= 1) x += __shfl_xor_sync(0xffffffffu, x, o);
            if (lane == 0) wpart[warp][i] = x;
        }
        __syncthreads();
        if (tid < 6) {
            float cn2 = 0.f;
            for (int w = 0; w < 5; w++) cn2 += wpart[w][tid];
            float cn = fmaxf(sqrtf(cn2), MINN);
            float pj = (cn > MAXN) ? MAXN / cn : 1.f;
            float nn = fmaxf(pj * cn, MINN);
            s_l[tid] = pj * artanhf_(nn) / nn;
        }
        __syncthreads();
    }
    // xt = relu(logmap0(res)); q/kv = logmap0(proj(expmap0(xt)))
    float xt[6];
    {
        #pragma unroll
        for (int v = 0; v < 6; v++) xt[v] = fmaxf(s_l[v] * cv[v], 0.f);
        #pragma unroll
        for (int i = 0; i < 6; i++) {
            float x = xt[i] * xt[i];
            #pragma unroll
            for (int o = 16; o > 0; o >>= 1) x += __shfl_xor_sync(0xffffffffu, x, o);
            if (lane == 0) wpart[warp][i] = x;
        }
        __syncthreads();
        if (tid < 6) {
            float n2 = 0.f;
            for (int w = 0; w < 5; w++) n2 += wpart[w][tid];
            float nx = fmaxf(sqrtf(n2), MINN);
            float ef = tanhf(nx) / nx;
            float en = ef * nx;
            float pj = (en > MAXN) ? MAXN / en : 1.f;
            float fn = fmaxf(pj * en, MINN);
            s_q[tid] = artanhf_(fn) / fn * pj * ef;
        }
        __syncthreads();
    }
    #pragma unroll
    for (int v = 0; v < 6; v++) skv[v][tid] = s_q[v] * xt[v];
    __syncthreads();

    // ---- attention: component t maps to (d = t/5, head = t%5) ----
    if (tid < 25) {
        int hd = tid / 5, k = tid % 5;
        float l = 0.f;
        #pragma unroll 8
        for (int d = 0; d < DD; d++)
            l += skv[0][d * 5 + hd] * skv[k + 1][d * 5 + hd];
        satt[tid] = l;
    }
    __syncthreads();
    if (tid < 5) {
        float m = -1e30f;
        #pragma unroll
        for (int k = 0; k < 5; k++) m = fmaxf(m, satt[tid * 5 + k]);
        float e[5], s = 0.f;
        #pragma unroll
        for (int k = 0; k < 5; k++) { e[k] = expf(satt[tid * 5 + k] - m); s += e[k]; }
        float inv = 1.f / s;
        #pragma unroll
        for (int k = 0; k < 5; k++) {
            float a = e[k] * inv;
            satt[tid * 5 + k] = a;
            if (att_out) att_out[(size_t)bn * 25 + tid * 5 + k] = a;
        }
    }
    __syncthreads();

    // ---- head-mean output + layer 2 (warp 0 only, 32-dim) ----
    if (tid < DD) {
        int d = tid;
        float o = 0.f;
        #pragma unroll
        for (int hd = 0; hd < 5; hd++) {
            float acc = 0.f;
            #pragma unroll
            for (int k = 0; k < 5; k++) acc += satt[hd * 5 + k] * skv[k + 1][d * 5 + hd];
            o += acc;
        }
        o *= 0.2f;
        // proj(expmap0(out32))
        float n2 = o * o;
        #pragma unroll
        for (int off = 16; off > 0; off >>= 1) n2 += __shfl_xor_sync(0xffffffffu, n2, off);
        float xn = fmaxf(sqrtf(n2), MINN);
        float e  = tanhf(xn) / xn;
        float pn = e * xn;
        float pj = (pn > MAXN) ? MAXN / pn : 1.f;
        float p   = e * pj * o;
        float p2n = fmaxf(pj * pn, MINN);
        // W2 @ p
        float m = 0.f;
        #pragma unroll 8
        for (int dd = 0; dd < DD; dd++) {
            float pd = __shfl_sync(0xffffffffu, p, dd);
            m += W2T[dd][tid] * pd;
        }
        float hbv = shb2[tid];
        float mxn2 = m * m, mh = m * hbv;
        #pragma unroll
        for (int off = 16; off > 0; off >>= 1) {
            mxn2 += __shfl_xor_sync(0xffffffffu, mxn2, off);
            mh   += __shfl_xor_sync(0xffffffffu, mh, off);
        }
        float mxn  = fmaxf(sqrtf(mxn2), MINN);
        float rfac = (mxn2 == 0.f) ? 0.f : tanhf(mxn / p2n * artanhf_(p2n)) / mxn;
        float rn  = rfac * mxn;
        float pjr = (rn > MAXN) ? MAXN / fmaxf(rn, MINN) : 1.f;
        float g   = pjr * rfac;
        float x2  = g * g * mxn2;
        float xy  = g * mh;
        float y2  = s_hbn22;
        float A   = 1.f + 2.f * xy + y2;
        float Bc  = 1.f - x2;
        float den = fmaxf(1.f + 2.f * xy + x2 * y2, MINN);
        float c_  = (A * g * m + Bc * hbv) / den;
        float cn2 = c_ * c_;
        #pragma unroll
        for (int off = 16; off > 0; off >>= 1) cn2 += __shfl_xor_sync(0xffffffffu, cn2, off);
        float cn  = fmaxf(sqrtf(cn2), MINN);
        float pj2 = (cn > MAXN) ? MAXN / cn : 1.f;
        float nnc = fmaxf(pj2 * cn, MINN);
        float u   = artanhf_(nnc) / nnc * pj2 * c_;
        float xtv = fmaxf(u, 0.f);
        float xn2 = xtv * xtv;
        #pragma unroll
        for (int off = 16; off > 0; off >>= 1) xn2 += __shfl_xor_sync(0xffffffffu, xn2, off);
        float nx  = fmaxf(sqrtf(xn2), MINN);
        float ef  = tanhf(nx) / nx;
        float en  = ef * nx;
        float pj3 = (en > MAXN) ? MAXN / en : 1.f;
        out[(size_t)bn * DD + tid] = pj3 * ef * xtv;
    }
}

extern "C" void kernel_launch(void* const* d_in, const int* in_sizes, int n_in,
                              void* d_out, int out_size) {
    const float* in_feats = (const float*)d_in[0];
    const float* in_nei   = (const float*)d_in[1];
    const float* W1       = (const float*)d_in[2];
    const float* b1       = (const float*)d_in[3];
    const float* W2       = (const float*)d_in[4];
    const float* b2       = (const float*)d_in[5];
    float* out = (float*)d_out;
    const int out_elems = BB * NN * DD;                 // 256000
    const int att_elems = BB * NN * 25;                 // 200000
    float* att = (out_size >= out_elems + att_elems) ? out + out_elems : nullptr;

    mha_hyp_kernel<<<BB * NN, NT>>>(in_feats, in_nei, W1, b1, W2, b2, out, att);
}

// round 4
// speedup vs baseline: 2.0439x; 2.0439x over previous
#include <cuda_runtime.h>
#include <math.h>

// MultiHeadsAttModel: hyperbolic (Poincare-ball) multi-head attention.
// out = concat( out f32 [4,2000,32], att f32 [4,2000,5,5] )

#define BB   4
#define NN   2000
#define KK   5
#define DD   32
#define M1   160
#define NT   160       // threads per block (5 warps)
#define MINN 1e-15f
#define MAXN 0.996f    // (1 - 4e-3)/sqrt(c), c = 1

__device__ __forceinline__ float artanhf_(float x) {
    const float lim = 1.0f - 1e-7f;
    x = fminf(fmaxf(x, -lim), lim);
    return 0.5f * (log1pf(x) - log1pf(-x));
}

__device__ __forceinline__ float wsum(float x) {
    #pragma unroll
    for (int o = 16; o > 0; o >>= 1) x += __shfl_xor_sync(0xffffffffu, x, o);
    return x;
}

__global__ void __launch_bounds__(NT, 7)
mha_hyp_kernel(const float* __restrict__ in_feats,
               const float* __restrict__ in_nei,
               const float* __restrict__ W1,
               const float* __restrict__ b1,
               const float* __restrict__ W2,
               const float* __restrict__ b2,
               float* __restrict__ out,
               float* __restrict__ att_out) {
    __shared__ float W1T[DD][M1 + 1];  // padded: conflict-free staging + matvec
    __shared__ float W2T[DD][DD + 1];
    __shared__ float sp[6][DD];        // agent + 5 neighbor points
    __shared__ float skv[6][M1 + 1];   // q(0) and kv(1..5)
    __shared__ float shb1[M1];
    __shared__ float shb2[DD];
    __shared__ float wpart[5][12];     // warp partials
    __shared__ float satt[25];
    __shared__ float s_pn[6], s_ps[6], s_cA[6], s_cB[6], s_ql[6];
    __shared__ float s_hbf1, s_hbn21, s_hbf2, s_hbn22;
    __shared__ int   snei[KK];

    const int tid  = threadIdx.x;
    const int lane = tid & 31;
    const int warp = tid >> 5;
    const int bn   = blockIdx.x;     // 0..7999
    const int b    = bn / NN;
    const int n    = bn - b * NN;

    // ---- stage weights into shared (transposed, padded -> conflict-free) ----
    for (int i = tid; i < M1 * DD; i += NT) W1T[i & 31][i >> 5] = W1[i];
    for (int i = tid; i < DD * DD; i += NT) W2T[i & 31][i >> 5] = W2[i];

    // ---- scan this agent's 5 one-hot rows (contiguous 10000 floats) ----
    // 2500 float4; row k = i/500 (2000 % 4 == 0). 4-deep batched streaming loads.
    {
        const float4* nin = (const float4*)(in_nei + (size_t)bn * (KK * NN));
        for (int base = 0; base < 2500; base += 4 * NT) {
            int i0 = base + tid;
            int i1 = i0 + NT, i2 = i0 + 2 * NT, i3 = i0 + 3 * NT;
            float4 v0 = make_float4(0.f, 0.f, 0.f, 0.f), v1 = v0, v2 = v0, v3 = v0;
            if (i0 < 2500) v0 = __ldcs(nin + i0);
            if (i1 < 2500) v1 = __ldcs(nin + i1);
            if (i2 < 2500) v2 = __ldcs(nin + i2);
            if (i3 < 2500) v3 = __ldcs(nin + i3);
            #pragma unroll
            for (int u = 0; u < 4; u++) {
                float4 v = (u == 0) ? v0 : (u == 1) ? v1 : (u == 2) ? v2 : v3;
                int i = i0 + u * NT;
                if (v.x != 0.f || v.y != 0.f || v.z != 0.f || v.w != 0.f) {
                    int r = (unsigned)i / 500u;
                    int c4 = i * 4 - r * 2000;
                    if (v.x != 0.f) snei[r] = c4;
                    if (v.y != 0.f) snei[r] = c4 + 1;
                    if (v.z != 0.f) snei[r] = c4 + 2;
                    if (v.w != 0.f) snei[r] = c4 + 3;
                }
            }
        }
    }
    float bt  = b1[tid];
    float bt2 = (tid < DD) ? b2[tid] : 0.f;
    __syncthreads();

    // ---- gather 6 input rows: v=0 agent, v=1..5 neighbors ----
    for (int j = tid; j < 6 * DD; j += NT) {
        int v = j >> 5, d = j & 31;
        int row = (v == 0) ? n : snei[v - 1];
        sp[v][d] = in_feats[((size_t)b * NN + row) * DD + d];
    }
    __syncthreads();

    // ---- phase 1: 32-dim norms (warp 0 only) + 160-dim b1 norm (all warps) ----
    if (warp == 0) {
        #pragma unroll
        for (int v = 0; v < 6; v++) {
            float x = wsum(sp[v][lane] * sp[v][lane]);
            if (lane == 0) wpart[0][v] = x;
        }
        float x7 = wsum(bt2 * bt2);
        if (lane == 0) wpart[0][7] = x7;
    }
    {
        float x6 = wsum(bt * bt);
        if (lane == 0) wpart[warp][6] = x6;
    }
    __syncthreads();
    if (tid < 6) {
        float n2 = wpart[0][tid];
        float xn = fmaxf(sqrtf(n2), MINN);
        float f1 = artanhf_(xn) / xn;          // logmap0 factor
        float fn = fmaxf(f1 * xn, MINN);
        float e  = tanhf(fn) / fn;             // expmap0 factor
        float pn = e * fn;
        float pj = (pn > MAXN) ? MAXN / pn : 1.f;
        s_ps[tid] = f1 * e * pj;
        s_pn[tid] = fmaxf(pj * pn, MINN);
    } else if (tid == 6) {
        float n2 = 0.f;
        #pragma unroll
        for (int w = 0; w < 5; w++) n2 += wpart[w][6];
        float bnn = fmaxf(sqrtf(n2), MINN);
        float e  = tanhf(bnn) / bnn;           // hb1 = proj(expmap0(b1))
        float pn = e * bnn;
        float pj = (pn > MAXN) ? MAXN / pn : 1.f;
        float f = e * pj;
        s_hbf1 = f; s_hbn21 = f * f * n2;
    } else if (tid == 7) {
        float n2 = wpart[0][7];
        float bnn = fmaxf(sqrtf(n2), MINN);
        float e  = tanhf(bnn) / bnn;           // hb2 = proj(expmap0(b2))
        float pn = e * bnn;
        float pj = (pn > MAXN) ? MAXN / pn : 1.f;
        float f = e * pj;
        s_hbf2 = f; s_hbn22 = f * f * n2;
    }
    __syncthreads();
    for (int j = tid; j < 6 * DD; j += NT)
        sp[j >> 5][j & 31] *= s_ps[j >> 5];
    shb1[tid] = bt * s_hbf1;
    if (tid < DD) shb2[tid] = bt2 * s_hbf2;
    __syncthreads();

    // ---- layer 1: mx = W1 @ p, 6 vectors; thread t owns output row t ----
    float mx[6] = {0.f, 0.f, 0.f, 0.f, 0.f, 0.f};
    #pragma unroll 8
    for (int d = 0; d < DD; d++) {
        float w = W1T[d][tid];
        #pragma unroll
        for (int v = 0; v < 6; v++) mx[v] += w * sp[v][d];
    }

    // ---- phase 2: ||mx||^2 (6) and, if bias nonzero, <mx,hb1> (6) ----
    const bool hb1z = (s_hbn21 == 0.f);
    {
        float hbv = shb1[tid];
        #pragma unroll
        for (int v = 0; v < 6; v++) {
            float x = wsum(mx[v] * mx[v]);
            if (lane == 0) wpart[warp][v] = x;
        }
        if (!hb1z) {
            #pragma unroll
            for (int v = 0; v < 6; v++) {
                float x = wsum(mx[v] * hbv);
                if (lane == 0) wpart[warp][6 + v] = x;
            }
        }
        __syncthreads();
        if (tid < 6) {
            float mxn2 = 0.f, mh = 0.f;
            #pragma unroll
            for (int w = 0; w < 5; w++) {
                mxn2 += wpart[w][tid];
                if (!hb1z) mh += wpart[w][6 + tid];
            }
            float xn  = s_pn[tid];
            float mxn = fmaxf(sqrtf(mxn2), MINN);
            float rfac = (mxn2 == 0.f) ? 0.f
                       : tanhf(mxn / xn * artanhf_(xn)) / mxn;     // mobius_matvec
            float rn = rfac * mxn;
            float pj = (rn > MAXN) ? MAXN / fmaxf(rn, MINN) : 1.f; // proj
            float g  = pj * rfac;                                  // res' = g*mx
            float x2 = g * g * mxn2;
            float xy = g * mh;
            float y2 = s_hbn21;
            float A   = 1.f + 2.f * xy + y2;
            float Bc  = 1.f - x2;
            float den = fmaxf(1.f + 2.f * xy + x2 * y2, MINN);     // mobius_add
            s_cA[tid] = A * g / den;
            s_cB[tid] = Bc / den;
        }
        __syncthreads();
    }

    // ---- phases 3+4 fused: cv = cA*mx + cB*hb1; reduce ||cv||^2 and ||max(cv,0)||^2
    float cv[6];
    {
        float hbv = shb1[tid];
        #pragma unroll
        for (int v = 0; v < 6; v++) cv[v] = s_cA[v] * mx[v] + s_cB[v] * hbv;
        #pragma unroll
        for (int v = 0; v < 6; v++) {
            float p = fmaxf(cv[v], 0.f);
            float x = wsum(cv[v] * cv[v]);
            float y = wsum(p * p);
            if (lane == 0) { wpart[warp][v] = x; wpart[warp][6 + v] = y; }
        }
        __syncthreads();
        if (tid < 6) {
            float cn2 = 0.f, pos2 = 0.f;
            #pragma unroll
            for (int w = 0; w < 5; w++) { cn2 += wpart[w][tid]; pos2 += wpart[w][6 + tid]; }
            float cn = fmaxf(sqrtf(cn2), MINN);
            float pj = (cn > MAXN) ? MAXN / cn : 1.f;
            float nn = fmaxf(pj * cn, MINN);
            float l  = pj * artanhf_(nn) / nn;       // logmap0(proj(res)); l >= 0
            // xt = relu(l*cv) = l*max(cv,0)  ->  ||xt|| = l*sqrt(pos2)
            float nx = fmaxf(l * sqrtf(pos2), MINN);
            float ef = tanhf(nx) / nx;
            float en = ef * nx;
            float pj2 = (en > MAXN) ? MAXN / en : 1.f;
            float fn = fmaxf(pj2 * en, MINN);
            float qf = artanhf_(fn) / fn * pj2 * ef;
            s_ql[tid] = qf * l;
        }
        __syncthreads();
    }
    #pragma unroll
    for (int v = 0; v < 6; v++) skv[v][tid] = s_ql[v] * fmaxf(cv[v], 0.f);
    __syncthreads();

    // ---- attention logits: thread t<25 -> (head = t/5, k = t%5) ----
    if (tid < 25) {
        int hd = tid / 5, k = tid % 5;
        float l = 0.f;
        #pragma unroll 8
        for (int d = 0; d < DD; d++)
            l += skv[0][d * 5 + hd] * skv[k + 1][d * 5 + hd];
        satt[tid] = l;
    }
    __syncthreads();
    if (tid < 5) {
        float m = -1e30f;
        #pragma unroll
        for (int k = 0; k < 5; k++) m = fmaxf(m, satt[tid * 5 + k]);
        float e[5], s = 0.f;
        #pragma unroll
        for (int k = 0; k < 5; k++) { e[k] = expf(satt[tid * 5 + k] - m); s += e[k]; }
        float inv = 1.f / s;
        #pragma unroll
        for (int k = 0; k < 5; k++) {
            float a = e[k] * inv;
            satt[tid * 5 + k] = a;
            if (att_out) att_out[(size_t)bn * 25 + tid * 5 + k] = a;
        }
    }
    __syncthreads();

    // ---- head-mean output + layer 2 (warp 0 only, 32-dim) ----
    if (tid < DD) {
        int d = tid;
        float o = 0.f;
        #pragma unroll
        for (int hd = 0; hd < 5; hd++) {
            float acc = 0.f;
            #pragma unroll
            for (int k = 0; k < 5; k++) acc += satt[hd * 5 + k] * skv[k + 1][d * 5 + hd];
            o += acc;
        }
        o *= 0.2f;
        // proj(expmap0(out32))
        float n2 = wsum(o * o);
        float xn = fmaxf(sqrtf(n2), MINN);
        float e  = tanhf(xn) / xn;
        float pn = e * xn;
        float pj = (pn > MAXN) ? MAXN / pn : 1.f;
        float p   = e * pj * o;
        float p2n = fmaxf(pj * pn, MINN);
        // W2 @ p
        float m = 0.f;
        #pragma unroll 8
        for (int dd = 0; dd < DD; dd++) {
            float pd = __shfl_sync(0xffffffffu, p, dd);
            m += W2T[dd][tid] * pd;
        }
        float hbv = shb2[tid];
        float mxn2 = wsum(m * m);
        float mh   = wsum(m * hbv);
        float mxn  = fmaxf(sqrtf(mxn2), MINN);
        float rfac = (mxn2 == 0.f) ? 0.f : tanhf(mxn / p2n * artanhf_(p2n)) / mxn;
        float rn  = rfac * mxn;
        float pjr = (rn > MAXN) ? MAXN / fmaxf(rn, MINN) : 1.f;
        float g   = pjr * rfac;
        float x2  = g * g * mxn2;
        float xy  = g * mh;
        float y2  = s_hbn22;
        float A   = 1.f + 2.f * xy + y2;
        float Bc  = 1.f - x2;
        float den = fmaxf(1.f + 2.f * xy + x2 * y2, MINN);
        float c_  = (A * g * m + Bc * hbv) / den;
        float cn2 = wsum(c_ * c_);
        float cn  = fmaxf(sqrtf(cn2), MINN);
        float pj2 = (cn > MAXN) ? MAXN / cn : 1.f;
        float nnc = fmaxf(pj2 * cn, MINN);
        float u   = artanhf_(nnc) / nnc * pj2 * c_;
        float xtv = fmaxf(u, 0.f);
        float xn2 = wsum(xtv * xtv);
        float nx  = fmaxf(sqrtf(xn2), MINN);
        float ef  = tanhf(nx) / nx;
        float en  = ef * nx;
        float pj3 = (en > MAXN) ? MAXN / en : 1.f;
        out[(size_t)bn * DD + tid] = pj3 * ef * xtv;
    }
}

extern "C" void kernel_launch(void* const* d_in, const int* in_sizes, int n_in,
                              void* d_out, int out_size) {
    const float* in_feats = (const float*)d_in[0];
    const float* in_nei   = (const float*)d_in[1];
    const float* W1       = (const float*)d_in[2];
    const float* b1       = (const float*)d_in[3];
    const float* W2       = (const float*)d_in[4];
    const float* b2       = (const float*)d_in[5];
    float* out = (float*)d_out;
    const int out_elems = BB * NN * DD;                 // 256000
    const int att_elems = BB * NN * 25;                 // 200000
    float* att = (out_size >= out_elems + att_elems) ? out + out_elems : nullptr;

    mha_hyp_kernel<<<BB * NN, NT>>>(in_feats, in_nei, W1, b1, W2, b2, out, att);
}

// round 5
// speedup vs baseline: 2.1738x; 1.0635x over previous
#include <cuda_runtime.h>
#include <math.h>

// MultiHeadsAttModel: hyperbolic (Poincare-ball) multi-head attention.
// out = concat( out f32 [4,2000,32], att f32 [4,2000,5,5] )
// Split: (A) pure-stream one-hot scan -> neighbor indices, (B) math pipeline.

#define BB   4
#define NN   2000
#define KK   5
#define DD   32
#define M1   160
#define NT   160       // compute kernel: threads per block (5 warps)
#define G    8         // agents per compute block
#define MINN 1e-15f
#define MAXN 0.996f    // (1 - 4e-3)/sqrt(c), c = 1

#define SCAN_T   256
#define SCAN_B8  8
#define TOT4     ((BB * NN * KK * NN) / 4)   // 20,000,000 uint4

__device__ int g_nei[BB * NN * KK];          // 40000 neighbor indices

__device__ __forceinline__ float artanhf_(float x) {
    const float lim = 1.0f - 1e-7f;
    x = fminf(fmaxf(x, -lim), lim);
    return 0.5f * (log1pf(x) - log1pf(-x));
}

__device__ __forceinline__ float wsum(float x) {
    #pragma unroll
    for (int o = 16; o > 0; o >>= 1) x += __shfl_xor_sync(0xffffffffu, x, o);
    return x;
}

// ---------------- Kernel A: streaming one-hot scan ----------------
__global__ void __launch_bounds__(SCAN_T)
scan_kernel(const uint4* __restrict__ nei) {
    unsigned b0 = blockIdx.x * (SCAN_T * SCAN_B8) + threadIdx.x;
    uint4 v[SCAN_B8];
    #pragma unroll
    for (int j = 0; j < SCAN_B8; j++) {
        unsigned i = b0 + j * SCAN_T;
        v[j] = (i < TOT4) ? __ldcs(nei + i) : make_uint4(0u, 0u, 0u, 0u);
    }
    #pragma unroll
    for (int j = 0; j < SCAN_B8; j++) {
        uint4 u = v[j];
        if ((u.x | u.y | u.z | u.w) != 0u) {
            unsigned i = b0 + j * SCAN_T;           // uint4 index; 2000 % 4 == 0
            unsigned r = i / 500u;                  // flat row = bn*KK + k
            unsigned c4 = i * 4u - r * 2000u;
            unsigned c = c4 + (u.x ? 0u : (u.y ? 1u : (u.z ? 2u : 3u)));
            g_nei[r] = (int)c;
        }
    }
}

// ---------------- Kernel B: hyperbolic attention math ----------------
__global__ void __launch_bounds__(NT, 7)
compute_kernel(const float* __restrict__ in_feats,
               const float* __restrict__ W1,
               const float* __restrict__ b1,
               const float* __restrict__ W2,
               const float* __restrict__ b2,
               float* __restrict__ out,
               float* __restrict__ att_out) {
    __shared__ float W1T[DD][M1 + 1];  // padded: conflict-free
    __shared__ float W2T[DD][DD + 1];
    __shared__ float sp[6][DD];        // agent + 5 neighbor points
    __shared__ float skv[6][M1 + 1];   // q(0) and kv(1..5)
    __shared__ float shb1[M1];
    __shared__ float shb2[DD];
    __shared__ float wpart[5][12];     // warp partials
    __shared__ float satt[25];
    __shared__ float s_pn[6], s_ps[6], s_cA[6], s_cB[6], s_ql[6];
    __shared__ float s_hbf1, s_hbn21, s_hbf2, s_hbn22;

    const int tid  = threadIdx.x;
    const int lane = tid & 31;
    const int warp = tid >> 5;

    // ---- stage weights (once per block, amortized over G agents) ----
    for (int i = tid; i < M1 * DD; i += NT) W1T[i & 31][i >> 5] = W1[i];
    for (int i = tid; i < DD * DD; i += NT) W2T[i & 31][i >> 5] = W2[i];

    float bt  = b1[tid];
    float bt2 = (tid < DD) ? b2[tid] : 0.f;

    // ---- bias points hb1 = proj(expmap0(b1)), hb2 = proj(expmap0(b2)) ----
    {
        float x6 = wsum(bt * bt);
        if (lane == 0) wpart[warp][6] = x6;
        if (warp == 0) {
            float x7 = wsum(bt2 * bt2);
            if (lane == 0) wpart[0][7] = x7;
        }
    }
    __syncthreads();
    if (tid == 0) {
        float n2 = 0.f;
        #pragma unroll
        for (int w = 0; w < 5; w++) n2 += wpart[w][6];
        float bnn = fmaxf(sqrtf(n2), MINN);
        float e  = tanhf(bnn) / bnn;
        float pn = e * bnn;
        float pj = (pn > MAXN) ? MAXN / pn : 1.f;
        float f = e * pj;
        s_hbf1 = f; s_hbn21 = f * f * n2;
    } else if (tid == 1) {
        float n2 = wpart[0][7];
        float bnn = fmaxf(sqrtf(n2), MINN);
        float e  = tanhf(bnn) / bnn;
        float pn = e * bnn;
        float pj = (pn > MAXN) ? MAXN / pn : 1.f;
        float f = e * pj;
        s_hbf2 = f; s_hbn22 = f * f * n2;
    }
    __syncthreads();
    shb1[tid] = bt * s_hbf1;
    if (tid < DD) shb2[tid] = bt2 * s_hbf2;
    const bool hb1z = (s_hbn21 == 0.f);
    __syncthreads();

    for (int a = 0; a < G; a++) {
        const int bn = blockIdx.x * G + a;     // 0..7999
        const int b  = bn / NN;
        const int n  = bn - b * NN;

        // ---- gather 6 input rows: v=0 agent, v=1..5 neighbors ----
        for (int j = tid; j < 6 * DD; j += NT) {
            int v = j >> 5, d = j & 31;
            int row = (v == 0) ? n : g_nei[bn * KK + v - 1];
            sp[v][d] = in_feats[((size_t)b * NN + row) * DD + d];
        }
        __syncthreads();

        // ---- phase 1: 32-dim norms (warp 0) ----
        if (warp == 0) {
            #pragma unroll
            for (int v = 0; v < 6; v++) {
                float x = wsum(sp[v][lane] * sp[v][lane]);
                if (lane == 0) wpart[0][v] = x;
            }
        }
        __syncthreads();
        if (tid < 6) {
            float n2 = wpart[0][tid];
            float xn = fmaxf(sqrtf(n2), MINN);
            float f1 = artanhf_(xn) / xn;          // logmap0 factor
            float fn = fmaxf(f1 * xn, MINN);
            float e  = tanhf(fn) / fn;             // expmap0 factor
            float pn = e * fn;
            float pj = (pn > MAXN) ? MAXN / pn : 1.f;
            s_ps[tid] = f1 * e * pj;
            s_pn[tid] = fmaxf(pj * pn, MINN);
        }
        __syncthreads();
        for (int j = tid; j < 6 * DD; j += NT)
            sp[j >> 5][j & 31] *= s_ps[j >> 5];
        __syncthreads();

        // ---- layer 1: mx = W1 @ p, 6 vectors; thread t owns output row t ----
        float mx[6] = {0.f, 0.f, 0.f, 0.f, 0.f, 0.f};
        #pragma unroll 8
        for (int d = 0; d < DD; d++) {
            float w = W1T[d][tid];
            #pragma unroll
            for (int v = 0; v < 6; v++) mx[v] += w * sp[v][d];
        }

        // ---- phase 2: ||mx||^2 (and <mx,hb1> if bias nonzero) ----
        {
            float hbv = shb1[tid];
            #pragma unroll
            for (int v = 0; v < 6; v++) {
                float x = wsum(mx[v] * mx[v]);
                if (lane == 0) wpart[warp][v] = x;
            }
            if (!hb1z) {
                #pragma unroll
                for (int v = 0; v < 6; v++) {
                    float x = wsum(mx[v] * hbv);
                    if (lane == 0) wpart[warp][6 + v] = x;
                }
            }
            __syncthreads();
            if (tid < 6) {
                float mxn2 = 0.f, mh = 0.f;
                #pragma unroll
                for (int w = 0; w < 5; w++) {
                    mxn2 += wpart[w][tid];
                    if (!hb1z) mh += wpart[w][6 + tid];
                }
                float xn  = s_pn[tid];
                float mxn = fmaxf(sqrtf(mxn2), MINN);
                float rfac = (mxn2 == 0.f) ? 0.f
                           : tanhf(mxn / xn * artanhf_(xn)) / mxn;     // mobius_matvec
                float rn = rfac * mxn;
                float pj = (rn > MAXN) ? MAXN / fmaxf(rn, MINN) : 1.f; // proj
                float g  = pj * rfac;                                  // res' = g*mx
                float x2 = g * g * mxn2;
                float xy = g * mh;
                float y2 = s_hbn21;
                float A   = 1.f + 2.f * xy + y2;
                float Bc  = 1.f - x2;
                float den = fmaxf(1.f + 2.f * xy + x2 * y2, MINN);     // mobius_add
                s_cA[tid] = A * g / den;
                s_cB[tid] = Bc / den;
            }
            __syncthreads();
        }

        // ---- phases 3+4: cv = cA*mx + cB*hb1; ||cv||^2 and ||max(cv,0)||^2 ----
        float cv[6];
        {
            float hbv = shb1[tid];
            #pragma unroll
            for (int v = 0; v < 6; v++) cv[v] = s_cA[v] * mx[v] + s_cB[v] * hbv;
            #pragma unroll
            for (int v = 0; v < 6; v++) {
                float p = fmaxf(cv[v], 0.f);
                float x = wsum(cv[v] * cv[v]);
                float y = wsum(p * p);
                if (lane == 0) { wpart[warp][v] = x; wpart[warp][6 + v] = y; }
            }
            __syncthreads();
            if (tid < 6) {
                float cn2 = 0.f, pos2 = 0.f;
                #pragma unroll
                for (int w = 0; w < 5; w++) { cn2 += wpart[w][tid]; pos2 += wpart[w][6 + tid]; }
                float cn = fmaxf(sqrtf(cn2), MINN);
                float pj = (cn > MAXN) ? MAXN / cn : 1.f;
                float nn = fmaxf(pj * cn, MINN);
                float l  = pj * artanhf_(nn) / nn;       // logmap0(proj(res)); l >= 0
                float nx = fmaxf(l * sqrtf(pos2), MINN); // ||relu(l*cv)||
                float ef = tanhf(nx) / nx;
                float en = ef * nx;
                float pj2 = (en > MAXN) ? MAXN / en : 1.f;
                float fn = fmaxf(pj2 * en, MINN);
                float qf = artanhf_(fn) / fn * pj2 * ef;
                s_ql[tid] = qf * l;
            }
            __syncthreads();
        }
        #pragma unroll
        for (int v = 0; v < 6; v++) skv[v][tid] = s_ql[v] * fmaxf(cv[v], 0.f);
        __syncthreads();

        // ---- attention logits: thread t<25 -> (head = t/5, k = t%5) ----
        if (tid < 25) {
            int hd = tid / 5, k = tid % 5;
            float l = 0.f;
            #pragma unroll 8
            for (int d = 0; d < DD; d++)
                l += skv[0][d * 5 + hd] * skv[k + 1][d * 5 + hd];
            satt[tid] = l;
        }
        __syncthreads();
        if (tid < 5) {
            float m = -1e30f;
            #pragma unroll
            for (int k = 0; k < 5; k++) m = fmaxf(m, satt[tid * 5 + k]);
            float e[5], s = 0.f;
            #pragma unroll
            for (int k = 0; k < 5; k++) { e[k] = expf(satt[tid * 5 + k] - m); s += e[k]; }
            float inv = 1.f / s;
            #pragma unroll
            for (int k = 0; k < 5; k++) {
                float av = e[k] * inv;
                satt[tid * 5 + k] = av;
                if (att_out) att_out[(size_t)bn * 25 + tid * 5 + k] = av;
            }
        }
        __syncthreads();

        // ---- head-mean output + layer 2 (warp 0 only, 32-dim) ----
        if (tid < DD) {
            int d = tid;
            float o = 0.f;
            #pragma unroll
            for (int hd = 0; hd < 5; hd++) {
                float acc = 0.f;
                #pragma unroll
                for (int k = 0; k < 5; k++) acc += satt[hd * 5 + k] * skv[k + 1][d * 5 + hd];
                o += acc;
            }
            o *= 0.2f;
            // proj(expmap0(out32))
            float n2 = wsum(o * o);
            float xn = fmaxf(sqrtf(n2), MINN);
            float e  = tanhf(xn) / xn;
            float pn = e * xn;
            float pj = (pn > MAXN) ? MAXN / pn : 1.f;
            float p   = e * pj * o;
            float p2n = fmaxf(pj * pn, MINN);
            // W2 @ p
            float m = 0.f;
            #pragma unroll 8
            for (int dd = 0; dd < DD; dd++) {
                float pd = __shfl_sync(0xffffffffu, p, dd);
                m += W2T[dd][tid] * pd;
            }
            float hbv = shb2[tid];
            float mxn2 = wsum(m * m);
            float mh   = wsum(m * hbv);
            float mxn  = fmaxf(sqrtf(mxn2), MINN);
            float rfac = (mxn2 == 0.f) ? 0.f : tanhf(mxn / p2n * artanhf_(p2n)) / mxn;
            float rn  = rfac * mxn;
            float pjr = (rn > MAXN) ? MAXN / fmaxf(rn, MINN) : 1.f;
            float g   = pjr * rfac;
            float x2  = g * g * mxn2;
            float xy  = g * mh;
            float y2  = s_hbn22;
            float A   = 1.f + 2.f * xy + y2;
            float Bc  = 1.f - x2;
            float den = fmaxf(1.f + 2.f * xy + x2 * y2, MINN);
            float c_  = (A * g * m + Bc * hbv) / den;
            float cn2 = wsum(c_ * c_);
            float cn  = fmaxf(sqrtf(cn2), MINN);
            float pj2 = (cn > MAXN) ? MAXN / cn : 1.f;
            float nnc = fmaxf(pj2 * cn, MINN);
            float u   = artanhf_(nnc) / nnc * pj2 * c_;
            float xtv = fmaxf(u, 0.f);
            float xn2 = wsum(xtv * xtv);
            float nx  = fmaxf(sqrtf(xn2), MINN);
            float ef  = tanhf(nx) / nx;
            float en  = ef * nx;
            float pj3 = (en > MAXN) ? MAXN / en : 1.f;
            out[(size_t)bn * DD + tid] = pj3 * ef * xtv;
        }
        // next iteration's first write (sp) is separated from warp0's reads
        // here by the next iteration's first __syncthreads()
    }
}

extern "C" void kernel_launch(void* const* d_in, const int* in_sizes, int n_in,
                              void* d_out, int out_size) {
    const float* in_feats = (const float*)d_in[0];
    const float* in_nei   = (const float*)d_in[1];
    const float* W1       = (const float*)d_in[2];
    const float* b1       = (const float*)d_in[3];
    const float* W2       = (const float*)d_in[4];
    const float* b2       = (const float*)d_in[5];
    float* out = (float*)d_out;
    const int out_elems = BB * NN * DD;                 // 256000
    const int att_elems = BB * NN * 25;                 // 200000
    float* att = (out_size >= out_elems + att_elems) ? out + out_elems : nullptr;

    const int scan_blocks = (TOT4 + SCAN_T * SCAN_B8 - 1) / (SCAN_T * SCAN_B8); // 9766
    scan_kernel<<<scan_blocks, SCAN_T>>>((const uint4*)in_nei);
    compute_kernel<<<(BB * NN) / G, NT>>>(in_feats, W1, b1, W2, b2, out, att);
}

// round 7
// speedup vs baseline: 3.3277x; 1.5309x over previous
#include <cuda_runtime.h>
#include <math.h>

// MultiHeadsAttModel: hyperbolic (Poincare-ball) multi-head attention.
// out = concat( out f32 [4,2000,32], att f32 [4,2000,5,5] )
// 3 kernels:
//   A) scan: pure-stream one-hot scan -> neighbor indices (HBM-bound, at floor)
//   B) phi:  per-node pipeline phi(m) = logmap0(hnn_layer(proj(expmap0(feats))))
//            computed ONCE per node (q and kv are the same function of the node)
//   C) att:  per-agent gather of 6 phi rows + attention + layer 2

#define BB   4
#define NN   2000
#define KK   5
#define DD   32
#define M1   160
#define MINN 1e-15f
#define MAXN 0.996f    // (1 - 4e-3)/sqrt(c), c = 1

#define SCAN_T   256
#define SCAN_B8  8
#define TOT4     ((BB * NN * KK * NN) / 4)   // 20,000,000 uint4

#define NNODE (BB * NN)                       // 8000
#define WPB   8                               // warps per block (B and C)

__device__ int   g_nei[NNODE * KK];           // 40000 neighbor indices
__device__ float g_phi[NNODE * M1];           // 8000 x 160 node embeddings

__device__ __forceinline__ float artanhf_(float x) {
    const float lim = 1.0f - 1e-7f;
    x = fminf(fmaxf(x, -lim), lim);
    return 0.5f * (log1pf(x) - log1pf(-x));
}

__device__ __forceinline__ float wsum(float x) {
    #pragma unroll
    for (int o = 16; o > 0; o >>= 1) x += __shfl_xor_sync(0xffffffffu, x, o);
    return x;
}

// ---------------- Kernel A: streaming one-hot scan ----------------
__global__ void __launch_bounds__(SCAN_T)
scan_kernel(const uint4* __restrict__ nei) {
    unsigned b0 = blockIdx.x * (SCAN_T * SCAN_B8) + threadIdx.x;
    uint4 v[SCAN_B8];
    #pragma unroll
    for (int j = 0; j < SCAN_B8; j++) {
        unsigned i = b0 + j * SCAN_T;
        v[j] = (i < TOT4) ? __ldcs(nei + i) : make_uint4(0u, 0u, 0u, 0u);
    }
    #pragma unroll
    for (int j = 0; j < SCAN_B8; j++) {
        uint4 u = v[j];
        if ((u.x | u.y | u.z | u.w) != 0u) {
            unsigned i = b0 + j * SCAN_T;           // uint4 index; 2000 % 4 == 0
            unsigned r = i / 500u;                  // flat row = bn*KK + k
            unsigned c4 = i * 4u - r * 2000u;
            unsigned c = c4 + (u.x ? 0u : (u.y ? 1u : (u.z ? 2u : 3u)));
            g_nei[r] = (int)c;
        }
    }
}

// ---------------- Kernel B: per-node phi, warp-autonomous ----------------
__global__ void __launch_bounds__(32 * WPB)
phi_kernel(const float* __restrict__ in_feats,
           const float* __restrict__ W1,
           const float* __restrict__ b1) {
    __shared__ float W1s[DD][M1 + 1];   // W1s[d][r] = W1[r][d]; pad -> conflict-free
    const int tid  = threadIdx.x;
    const int lane = tid & 31;
    const int warp = tid >> 5;
    for (int i = tid; i < M1 * DD; i += 32 * WPB) W1s[i & 31][i >> 5] = W1[i];
    __syncthreads();

    const int node = blockIdx.x * WPB + warp;      // < 8000 (grid exact)

    // hyperbolic bias point hb1 = proj(expmap0(b1)), per-lane rows r = lane+32j
    float b1v[5];
    float bsq = 0.f;
    #pragma unroll
    for (int j = 0; j < 5; j++) { b1v[j] = b1[lane + 32 * j]; bsq += b1v[j] * b1v[j]; }
    float bn2 = wsum(bsq);
    float hbn2;
    {
        float bnn = fmaxf(sqrtf(bn2), MINN);
        float e  = tanhf(bnn) / bnn;
        float pn = e * bnn;
        float pj = (pn > MAXN) ? MAXN / pn : 1.f;
        float f  = e * pj;
        hbn2 = f * f * bn2;
        #pragma unroll
        for (int j = 0; j < 5; j++) b1v[j] *= f;
    }

    // p = proj(expmap0(logmap0(x)))
    float x  = in_feats[node * DD + lane];
    float n2 = wsum(x * x);
    float ps, xnc;
    {
        float xn = fmaxf(sqrtf(n2), MINN);
        float f1 = artanhf_(xn) / xn;            // logmap0
        float fn = fmaxf(f1 * xn, MINN);
        float e  = tanhf(fn) / fn;               // expmap0
        float pn = e * fn;
        float pj = (pn > MAXN) ? MAXN / pn : 1.f;
        ps  = f1 * e * pj;
        xnc = fmaxf(pj * pn, MINN);
    }
    float p = ps * x;

    // mx = W1 @ p : lane owns rows lane+32j
    float mx[5] = {0.f, 0.f, 0.f, 0.f, 0.f};
    #pragma unroll
    for (int d = 0; d < DD; d++) {
        float pd = __shfl_sync(0xffffffffu, p, d);
        #pragma unroll
        for (int j = 0; j < 5; j++) mx[j] += W1s[d][lane + 32 * j] * pd;
    }

    float s1 = 0.f, s2 = 0.f;
    #pragma unroll
    for (int j = 0; j < 5; j++) { s1 += mx[j] * mx[j]; s2 += mx[j] * b1v[j]; }
    float mxn2 = wsum(s1);
    float mh   = wsum(s2);

    float cA, cB;
    {
        float mxn  = fmaxf(sqrtf(mxn2), MINN);
        float rfac = (mxn2 == 0.f) ? 0.f
                   : tanhf(mxn / xnc * artanhf_(xnc)) / mxn;       // mobius_matvec
        float rn = rfac * mxn;
        float pj = (rn > MAXN) ? MAXN / fmaxf(rn, MINN) : 1.f;     // proj
        float g  = pj * rfac;
        float x2 = g * g * mxn2;
        float xy = g * mh;
        float y2 = hbn2;
        float A   = 1.f + 2.f * xy + y2;
        float Bc  = 1.f - x2;
        float den = fmaxf(1.f + 2.f * xy + x2 * y2, MINN);         // mobius_add
        cA = A * g / den;
        cB = Bc / den;
    }

    float cv[5];
    float c1 = 0.f, c2 = 0.f;
    #pragma unroll
    for (int j = 0; j < 5; j++) {
        cv[j] = cA * mx[j] + cB * b1v[j];
        float pp = fmaxf(cv[j], 0.f);
        c1 += cv[j] * cv[j];
        c2 += pp * pp;
    }
    float cn2  = wsum(c1);
    float pos2 = wsum(c2);
    float ql;
    {
        float cn = fmaxf(sqrtf(cn2), MINN);
        float pj = (cn > MAXN) ? MAXN / cn : 1.f;
        float nn = fmaxf(pj * cn, MINN);
        float l  = pj * artanhf_(nn) / nn;         // logmap0(proj(res)); l >= 0
        float nx = fmaxf(l * sqrtf(pos2), MINN);   // ||relu(l*cv)||
        float ef = tanhf(nx) / nx;
        float en = ef * nx;
        float pj2 = (en > MAXN) ? MAXN / en : 1.f;
        float fn = fmaxf(pj2 * en, MINN);
        ql = artanhf_(fn) / fn * pj2 * ef * l;
    }
    #pragma unroll
    for (int j = 0; j < 5; j++)
        g_phi[node * M1 + lane + 32 * j] = ql * fmaxf(cv[j], 0.f);
}

// ---------------- Kernel C: attention + layer 2, warp-per-agent ----------------
#define SKST 161   // padded row stride: kills k-wise bank conflicts

__global__ void __launch_bounds__(32 * WPB)
att_kernel(const float* __restrict__ W2,
           const float* __restrict__ b2,
           float* __restrict__ out,
           float* __restrict__ att_out) {
    __shared__ float W2s[DD][DD + 1];
    __shared__ float skv[WPB][6][SKST];
    __shared__ float satt[WPB][32];

    const int tid  = threadIdx.x;
    const int lane = tid & 31;
    const int warp = tid >> 5;
    for (int i = tid; i < DD * DD; i += 32 * WPB) W2s[i & 31][i >> 5] = W2[i];
    __syncthreads();

    const int bn = blockIdx.x * WPB + warp;        // < 8000
    const int b  = bn / NN;

    // gather q(phi[bn]) and kv(phi[neighbors])
    #pragma unroll
    for (int v = 0; v < 6; v++) {
        int row = (v == 0) ? bn : b * NN + g_nei[bn * KK + v - 1];
        #pragma unroll
        for (int j = 0; j < 5; j++)
            skv[warp][v][lane + 32 * j] = g_phi[row * M1 + lane + 32 * j];
    }
    __syncwarp();

    // logits: lane < 25 -> (hd = lane/5, k = lane%5)
    if (lane < 25) {
        int hd = lane / 5, k = lane - hd * 5;
        float l = 0.f;
        #pragma unroll 8
        for (int d = 0; d < DD; d++)
            l += skv[warp][0][d * 5 + hd] * skv[warp][k + 1][d * 5 + hd];
        satt[warp][lane] = l;
    }
    __syncwarp();
    if (lane < 5) {
        float m = -1e30f;
        #pragma unroll
        for (int k = 0; k < 5; k++) m = fmaxf(m, satt[warp][lane * 5 + k]);
        float e[5], s = 0.f;
        #pragma unroll
        for (int k = 0; k < 5; k++) { e[k] = expf(satt[warp][lane * 5 + k] - m); s += e[k]; }
        float inv = 1.f / s;
        #pragma unroll
        for (int k = 0; k < 5; k++) {
            float a = e[k] * inv;
            satt[warp][lane * 5 + k] = a;
            if (att_out) att_out[(size_t)bn * 25 + lane * 5 + k] = a;
        }
    }
    __syncwarp();

    // head-mean output (lane = output dim d)
    float o = 0.f;
    #pragma unroll
    for (int hd = 0; hd < 5; hd++) {
        float acc = 0.f;
        #pragma unroll
        for (int k = 0; k < 5; k++)
            acc += satt[warp][hd * 5 + k] * skv[warp][k + 1][lane * 5 + hd];
        o += acc;
    }
    o *= 0.2f;

    // hb2 = proj(expmap0(b2))
    float bt2 = b2[lane];
    float hbv, hbn22;
    {
        float n2b = wsum(bt2 * bt2);
        float bnn = fmaxf(sqrtf(n2b), MINN);
        float e  = tanhf(bnn) / bnn;
        float pn = e * bnn;
        float pj = (pn > MAXN) ? MAXN / pn : 1.f;
        float f  = e * pj;
        hbv = bt2 * f;
        hbn22 = f * f * n2b;
    }

    // layer 2
    float n2 = wsum(o * o);
    float xn = fmaxf(sqrtf(n2), MINN);
    float e  = tanhf(xn) / xn;
    float pn = e * xn;
    float pj = (pn > MAXN) ? MAXN / pn : 1.f;
    float p   = e * pj * o;                    // proj(expmap0(out32))
    float p2n = fmaxf(pj * pn, MINN);
    float m = 0.f;
    #pragma unroll 8
    for (int dd = 0; dd < DD; dd++) {
        float pd = __shfl_sync(0xffffffffu, p, dd);
        m += W2s[dd][lane] * pd;               // W2 @ p
    }
    float mxn2 = wsum(m * m);
    float mh   = wsum(m * hbv);
    float mxn  = fmaxf(sqrtf(mxn2), MINN);
    float rfac = (mxn2 == 0.f) ? 0.f : tanhf(mxn / p2n * artanhf_(p2n)) / mxn;
    float rn  = rfac * mxn;
    float pjr = (rn > MAXN) ? MAXN / fmaxf(rn, MINN) : 1.f;
    float g   = pjr * rfac;
    float x2  = g * g * mxn2;
    float xy  = g * mh;
    float y2  = hbn22;
    float A   = 1.f + 2.f * xy + y2;
    float Bc  = 1.f - x2;
    float den = fmaxf(1.f + 2.f * xy + x2 * y2, MINN);
    float c_  = (A * g * m + Bc * hbv) / den;
    float cn2 = wsum(c_ * c_);
    float cn  = fmaxf(sqrtf(cn2), MINN);
    float pj2 = (cn > MAXN) ? MAXN / cn : 1.f;
    float nnc = fmaxf(pj2 * cn, MINN);
    float u   = artanhf_(nnc) / nnc * pj2 * c_;
    float xtv = fmaxf(u, 0.f);
    float xn2 = wsum(xtv * xtv);
    float nx  = fmaxf(sqrtf(xn2), MINN);
    float ef  = tanhf(nx) / nx;
    float en  = ef * nx;
    float pj3 = (en > MAXN) ? MAXN / en : 1.f;
    out[(size_t)bn * DD + lane] = pj3 * ef * xtv;
}

extern "C" void kernel_launch(void* const* d_in, const int* in_sizes, int n_in,
                              void* d_out, int out_size) {
    const float* in_feats = (const float*)d_in[0];
    const float* in_nei   = (const float*)d_in[1];
    const float* W1       = (const float*)d_in[2];
    const float* b1       = (const float*)d_in[3];
    const float* W2       = (const float*)d_in[4];
    const float* b2       = (const float*)d_in[5];
    float* out = (float*)d_out;
    const int out_elems = BB * NN * DD;                 // 256000
    const int att_elems = BB * NN * 25;                 // 200000
    float* att = (out_size >= out_elems + att_elems) ? out + out_elems : nullptr;

    const int scan_blocks = (TOT4 + SCAN_T * SCAN_B8 - 1) / (SCAN_T * SCAN_B8); // 9766
    scan_kernel<<<scan_blocks, SCAN_T>>>((const uint4*)in_nei);
    phi_kernel<<<NNODE / WPB, 32 * WPB>>>(in_feats, W1, b1);
    att_kernel<<<NNODE / WPB, 32 * WPB>>>(W2, b2, out, att);
}

// round 8
// speedup vs baseline: 3.5099x; 1.0547x over previous
#include <cuda_runtime.h>
#include <math.h>

// MultiHeadsAttModel: hyperbolic (Poincare-ball) multi-head attention.
// out = concat( out f32 [4,2000,32], att f32 [4,2000,5,5] )
// 2 kernels:
//   A) fused scan+phi: heterogeneous grid. phi blocks (first 1000) compute the
//      per-node embedding phi(m) = logmap0(hnn_layer(proj(expmap0(feats))))
//      and hide completely under the HBM-bound one-hot scan (issue% ~13).
//   B) att: per-agent gather of 6 phi rows + attention + layer 2.

#define BB   4
#define NN   2000
#define KK   5
#define DD   32
#define M1   160
#define MINN 1e-15f
#define MAXN 0.996f    // (1 - 4e-3)/sqrt(c), c = 1

#define SCAN_T   256
#define SCAN_B8  8
#define TOT4     ((BB * NN * KK * NN) / 4)   // 20,000,000 uint4
#define SCAN_BLOCKS ((TOT4 + SCAN_T * SCAN_B8 - 1) / (SCAN_T * SCAN_B8))  // 9766

#define NNODE (BB * NN)                       // 8000
#define WPB   8                               // warps per block
#define PHI_BLOCKS (NNODE / WPB)              // 1000

__device__ int   g_nei[NNODE * KK];           // 40000 neighbor indices
__device__ float g_phi[NNODE * M1];           // 8000 x 160 node embeddings

__device__ __forceinline__ float artanhf_(float x) {
    const float lim = 1.0f - 1e-7f;
    x = fminf(fmaxf(x, -lim), lim);
    return 0.5f * (log1pf(x) - log1pf(-x));
}

__device__ __forceinline__ float wsum(float x) {
    #pragma unroll
    for (int o = 16; o > 0; o >>= 1) x += __shfl_xor_sync(0xffffffffu, x, o);
    return x;
}

// ---------------- Kernel A: fused phi (blocks [0,1000)) + scan (rest) ----------------
__global__ void __launch_bounds__(SCAN_T)
scan_phi_kernel(const uint4* __restrict__ nei,
                const float* __restrict__ in_feats,
                const float* __restrict__ W1,
                const float* __restrict__ b1) {
    __shared__ float W1s[DD][M1 + 1];   // used by phi blocks only

    if (blockIdx.x >= PHI_BLOCKS) {
        // ================= scan role: streaming one-hot scan =================
        unsigned sb = blockIdx.x - PHI_BLOCKS;
        unsigned b0 = sb * (SCAN_T * SCAN_B8) + threadIdx.x;
        uint4 v[SCAN_B8];
        #pragma unroll
        for (int j = 0; j < SCAN_B8; j++) {
            unsigned i = b0 + j * SCAN_T;
            v[j] = (i < TOT4) ? __ldcs(nei + i) : make_uint4(0u, 0u, 0u, 0u);
        }
        #pragma unroll
        for (int j = 0; j < SCAN_B8; j++) {
            uint4 u = v[j];
            if ((u.x | u.y | u.z | u.w) != 0u) {
                unsigned i = b0 + j * SCAN_T;        // uint4 index; 2000 % 4 == 0
                unsigned r = i / 500u;               // flat row = bn*KK + k
                unsigned c4 = i * 4u - r * 2000u;
                unsigned c = c4 + (u.x ? 0u : (u.y ? 1u : (u.z ? 2u : 3u)));
                g_nei[r] = (int)c;
            }
        }
        return;
    }

    // ================= phi role: per-node embedding, warp-autonomous =================
    const int tid  = threadIdx.x;
    const int lane = tid & 31;
    const int warp = tid >> 5;
    for (int i = tid; i < M1 * DD; i += 32 * WPB) W1s[i & 31][i >> 5] = W1[i];
    __syncthreads();

    const int node = blockIdx.x * WPB + warp;      // < 8000

    // hyperbolic bias point hb1 = proj(expmap0(b1)); lane owns rows lane+32j
    float b1v[5];
    float bsq = 0.f;
    #pragma unroll
    for (int j = 0; j < 5; j++) { b1v[j] = b1[lane + 32 * j]; bsq += b1v[j] * b1v[j]; }
    float bn2 = wsum(bsq);
    float hbn2;
    {
        float bnn = fmaxf(sqrtf(bn2), MINN);
        float e  = tanhf(bnn) / bnn;
        float pn = e * bnn;
        float pj = (pn > MAXN) ? MAXN / pn : 1.f;
        float f  = e * pj;
        hbn2 = f * f * bn2;
        #pragma unroll
        for (int j = 0; j < 5; j++) b1v[j] *= f;
    }

    // p = proj(expmap0(logmap0(x)))
    float x  = in_feats[node * DD + lane];
    float n2 = wsum(x * x);
    float ps, xnc;
    {
        float xn = fmaxf(sqrtf(n2), MINN);
        float f1 = artanhf_(xn) / xn;            // logmap0
        float fn = fmaxf(f1 * xn, MINN);
        float e  = tanhf(fn) / fn;               // expmap0
        float pn = e * fn;
        float pj = (pn > MAXN) ? MAXN / pn : 1.f;
        ps  = f1 * e * pj;
        xnc = fmaxf(pj * pn, MINN);
    }
    float p = ps * x;

    // mx = W1 @ p : lane owns rows lane+32j
    float mx[5] = {0.f, 0.f, 0.f, 0.f, 0.f};
    #pragma unroll
    for (int d = 0; d < DD; d++) {
        float pd = __shfl_sync(0xffffffffu, p, d);
        #pragma unroll
        for (int j = 0; j < 5; j++) mx[j] += W1s[d][lane + 32 * j] * pd;
    }

    float s1 = 0.f, s2 = 0.f;
    #pragma unroll
    for (int j = 0; j < 5; j++) { s1 += mx[j] * mx[j]; s2 += mx[j] * b1v[j]; }
    float mxn2 = wsum(s1);
    float mh   = wsum(s2);

    float cA, cB;
    {
        float mxn  = fmaxf(sqrtf(mxn2), MINN);
        float rfac = (mxn2 == 0.f) ? 0.f
                   : tanhf(mxn / xnc * artanhf_(xnc)) / mxn;       // mobius_matvec
        float rn = rfac * mxn;
        float pj = (rn > MAXN) ? MAXN / fmaxf(rn, MINN) : 1.f;     // proj
        float g  = pj * rfac;
        float x2 = g * g * mxn2;
        float xy = g * mh;
        float y2 = hbn2;
        float A   = 1.f + 2.f * xy + y2;
        float Bc  = 1.f - x2;
        float den = fmaxf(1.f + 2.f * xy + x2 * y2, MINN);         // mobius_add
        cA = A * g / den;
        cB = Bc / den;
    }

    float cv[5];
    float c1 = 0.f, c2 = 0.f;
    #pragma unroll
    for (int j = 0; j < 5; j++) {
        cv[j] = cA * mx[j] + cB * b1v[j];
        float pp = fmaxf(cv[j], 0.f);
        c1 += cv[j] * cv[j];
        c2 += pp * pp;
    }
    float cn2  = wsum(c1);
    float pos2 = wsum(c2);
    float ql;
    {
        float cn = fmaxf(sqrtf(cn2), MINN);
        float pj = (cn > MAXN) ? MAXN / cn : 1.f;
        float nn = fmaxf(pj * cn, MINN);
        float l  = pj * artanhf_(nn) / nn;         // logmap0(proj(res)); l >= 0
        float nx = fmaxf(l * sqrtf(pos2), MINN);   // ||relu(l*cv)||
        float ef = tanhf(nx) / nx;
        float en = ef * nx;
        float pj2 = (en > MAXN) ? MAXN / en : 1.f;
        float fn = fmaxf(pj2 * en, MINN);
        ql = artanhf_(fn) / fn * pj2 * ef * l;
    }
    #pragma unroll
    for (int j = 0; j < 5; j++)
        g_phi[node * M1 + lane + 32 * j] = ql * fmaxf(cv[j], 0.f);
}

// ---------------- Kernel B: attention + layer 2, warp-per-agent ----------------
#define SKST 161   // padded row stride: kills k-wise bank conflicts

__global__ void __launch_bounds__(32 * WPB)
att_kernel(const float* __restrict__ W2,
           const float* __restrict__ b2,
           float* __restrict__ out,
           float* __restrict__ att_out) {
    __shared__ float W2s[DD][DD + 1];
    __shared__ float skv[WPB][6][SKST];
    __shared__ float satt[WPB][32];

    const int tid  = threadIdx.x;
    const int lane = tid & 31;
    const int warp = tid >> 5;
    for (int i = tid; i < DD * DD; i += 32 * WPB) W2s[i & 31][i >> 5] = W2[i];
    __syncthreads();

    const int bn = blockIdx.x * WPB + warp;        // < 8000
    const int b  = bn / NN;

    // gather q(phi[bn]) and kv(phi[neighbors])
    #pragma unroll
    for (int v = 0; v < 6; v++) {
        int row = (v == 0) ? bn : b * NN + g_nei[bn * KK + v - 1];
        #pragma unroll
        for (int j = 0; j < 5; j++)
            skv[warp][v][lane + 32 * j] = g_phi[row * M1 + lane + 32 * j];
    }
    __syncwarp();

    // logits: lane < 25 -> (hd = lane/5, k = lane%5)
    if (lane < 25) {
        int hd = lane / 5, k = lane - hd * 5;
        float l = 0.f;
        #pragma unroll 8
        for (int d = 0; d < DD; d++)
            l += skv[warp][0][d * 5 + hd] * skv[warp][k + 1][d * 5 + hd];
        satt[warp][lane] = l;
    }
    __syncwarp();
    if (lane < 5) {
        float m = -1e30f;
        #pragma unroll
        for (int k = 0; k < 5; k++) m = fmaxf(m, satt[warp][lane * 5 + k]);
        float e[5], s = 0.f;
        #pragma unroll
        for (int k = 0; k < 5; k++) { e[k] = expf(satt[warp][lane * 5 + k] - m); s += e[k]; }
        float inv = 1.f / s;
        #pragma unroll
        for (int k = 0; k < 5; k++) {
            float a = e[k] * inv;
            satt[warp][lane * 5 + k] = a;
            if (att_out) att_out[(size_t)bn * 25 + lane * 5 + k] = a;
        }
    }
    __syncwarp();

    // head-mean output (lane = output dim d)
    float o = 0.f;
    #pragma unroll
    for (int hd = 0; hd < 5; hd++) {
        float acc = 0.f;
        #pragma unroll
        for (int k = 0; k < 5; k++)
            acc += satt[warp][hd * 5 + k] * skv[warp][k + 1][lane * 5 + hd];
        o += acc;
    }
    o *= 0.2f;

    // hb2 = proj(expmap0(b2))
    float bt2 = b2[lane];
    float hbv, hbn22;
    {
        float n2b = wsum(bt2 * bt2);
        float bnn = fmaxf(sqrtf(n2b), MINN);
        float e  = tanhf(bnn) / bnn;
        float pn = e * bnn;
        float pj = (pn > MAXN) ? MAXN / pn : 1.f;
        float f  = e * pj;
        hbv = bt2 * f;
        hbn22 = f * f * n2b;
    }

    // layer 2
    float n2 = wsum(o * o);
    float xn = fmaxf(sqrtf(n2), MINN);
    float e  = tanhf(xn) / xn;
    float pn = e * xn;
    float pj = (pn > MAXN) ? MAXN / pn : 1.f;
    float p   = e * pj * o;                    // proj(expmap0(out32))
    float p2n = fmaxf(pj * pn, MINN);
    float m = 0.f;
    #pragma unroll 8
    for (int dd = 0; dd < DD; dd++) {
        float pd = __shfl_sync(0xffffffffu, p, dd);
        m += W2s[dd][lane] * pd;               // W2 @ p
    }
    float mxn2 = wsum(m * m);
    float mh   = wsum(m * hbv);
    float mxn  = fmaxf(sqrtf(mxn2), MINN);
    float rfac = (mxn2 == 0.f) ? 0.f : tanhf(mxn / p2n * artanhf_(p2n)) / mxn;
    float rn  = rfac * mxn;
    float pjr = (rn > MAXN) ? MAXN / fmaxf(rn, MINN) : 1.f;
    float g   = pjr * rfac;
    float x2  = g * g * mxn2;
    float xy  = g * mh;
    float y2  = hbn22;
    float A   = 1.f + 2.f * xy + y2;
    float Bc  = 1.f - x2;
    float den = fmaxf(1.f + 2.f * xy + x2 * y2, MINN);
    float c_  = (A * g * m + Bc * hbv) / den;
    float cn2 = wsum(c_ * c_);
    float cn  = fmaxf(sqrtf(cn2), MINN);
    float pj2 = (cn > MAXN) ? MAXN / cn : 1.f;
    float nnc = fmaxf(pj2 * cn, MINN);
    float u   = artanhf_(nnc) / nnc * pj2 * c_;
    float xtv = fmaxf(u, 0.f);
    float xn2 = wsum(xtv * xtv);
    float nx  = fmaxf(sqrtf(xn2), MINN);
    float ef  = tanhf(nx) / nx;
    float en  = ef * nx;
    float pj3 = (en > MAXN) ? MAXN / en : 1.f;
    out[(size_t)bn * DD + lane] = pj3 * ef * xtv;
}

extern "C" void kernel_launch(void* const* d_in, const int* in_sizes, int n_in,
                              void* d_out, int out_size) {
    const float* in_feats = (const float*)d_in[0];
    const float* in_nei   = (const float*)d_in[1];
    const float* W1       = (const float*)d_in[2];
    const float* b1       = (const float*)d_in[3];
    const float* W2       = (const float*)d_in[4];
    const float* b2       = (const float*)d_in[5];
    float* out = (float*)d_out;
    const int out_elems = BB * NN * DD;                 // 256000
    const int att_elems = BB * NN * 25;                 // 200000
    float* att = (out_size >= out_elems + att_elems) ? out + out_elems : nullptr;

    scan_phi_kernel<<<PHI_BLOCKS + SCAN_BLOCKS, SCAN_T>>>(
        (const uint4*)in_nei, in_feats, W1, b1);
    att_kernel<<<NNODE / WPB, 32 * WPB>>>(W2, b2, out, att);
}